// round 1
// baseline (speedup 1.0000x reference)
#include <cuda_runtime.h>

#define NN 32768   // columns
#define MM 512     // rows of A / X
#define KK 32      // inner dim / output rows
#define NITER 200

// ---- device-global scratch (no allocations allowed) ----
__device__ float g_step;
__device__ __align__(16) unsigned long long g_AtA_p[32][16];   // [j][i2] = (AtA[2i2][j], AtA[2i2+1][j]) packed f32x2
__device__ unsigned long long g_AtX_p[16][NN];                 // [i2][n] = (AtX[2i2][n], AtX[2i2+1][n]) packed f32x2

// ---- packed f32x2 helpers (Blackwell sm_100+) ----
__device__ __forceinline__ unsigned long long pack2f(float lo, float hi) {
    unsigned long long r;
    asm("mov.b64 %0, {%1, %2};" : "=l"(r) : "r"(__float_as_uint(lo)), "r"(__float_as_uint(hi)));
    return r;
}
__device__ __forceinline__ unsigned long long dup2f(float v) {
    unsigned long long r;
    unsigned int u = __float_as_uint(v);
    asm("mov.b64 %0, {%1, %1};" : "=l"(r) : "r"(u));
    return r;
}
__device__ __forceinline__ void unpack2f(unsigned long long p, float& lo, float& hi) {
    unsigned int a, b;
    asm("mov.b64 {%0, %1}, %2;" : "=r"(a), "=r"(b) : "l"(p));
    lo = __uint_as_float(a);
    hi = __uint_as_float(b);
}
__device__ __forceinline__ unsigned long long fma2(unsigned long long a, unsigned long long b, unsigned long long c) {
    unsigned long long d;
    asm("fma.rn.f32x2 %0, %1, %2, %3;" : "=l"(d) : "l"(a), "l"(b), "l"(c));
    return d;
}

// ============================================================================
// Kernel 1: AtA = A^T A  (32x32), packed layout, and step = 1/||AtA||_2
// via power iteration (symmetric PSD, large spectral gap -> converges fast).
// ============================================================================
__global__ void setup_kernel(const float* __restrict__ A) {
    __shared__ float sAtA[32][32];
    int t = threadIdx.x;           // 1024 threads
    int i = t >> 5, j = t & 31;
    float acc = 0.0f;
    for (int m = 0; m < MM; m++)
        acc = fmaf(A[m * KK + i], A[m * KK + j], acc);
    sAtA[i][j] = acc;
    __syncthreads();

    // packed AtA: g_AtA_p[j][i2] = (AtA[2i2][j], AtA[2i2+1][j])
    if (t < 512) {
        int jj = t >> 4, i2 = t & 15;
        g_AtA_p[jj][i2] = pack2f(sAtA[2 * i2][jj], sAtA[2 * i2 + 1][jj]);
    }

    // power iteration on warp 0: lane l holds v[l]
    if (t < 32) {
        int l = t;
        float v = 1.0f;
        float lam = 1.0f;
        for (int it = 0; it < 200; it++) {
            float w = 0.0f;
            #pragma unroll
            for (int jj = 0; jj < 32; jj++) {
                float vj = __shfl_sync(0xffffffffu, v, jj);
                w = fmaf(sAtA[l][jj], vj, w);
            }
            float n2 = w * w;
            #pragma unroll
            for (int o = 16; o; o >>= 1)
                n2 += __shfl_xor_sync(0xffffffffu, n2, o);
            lam = sqrtf(n2);
            v = w / lam;   // lam = ||AtA v|| with ||v||=1 -> lambda_max
        }
        if (l == 0) g_step = 1.0f / lam;
    }
}

// ============================================================================
// Kernel 2: AtX = A^T X, stored packed over row-pairs for the FISTA kernel.
// One thread per column n. A staged through shared in 64-row chunks, packed.
// ============================================================================
__global__ void __launch_bounds__(256) atx_kernel(const float* __restrict__ X,
                                                  const float* __restrict__ A) {
    __shared__ __align__(16) unsigned long long sAp[64][16];  // [m][i2] = (A[m][2i2], A[m][2i2+1])
    const int n = blockIdx.x * 256 + threadIdx.x;

    unsigned long long acc[16];
    #pragma unroll
    for (int i2 = 0; i2 < 16; i2++) acc[i2] = 0ull;

    const unsigned long long* A2 = (const unsigned long long*)A;  // pairs of floats, 8B aligned

    for (int m0 = 0; m0 < MM; m0 += 64) {
        __syncthreads();
        #pragma unroll
        for (int k = 0; k < 4; k++) {
            int idx = threadIdx.x + k * 256;   // 1024 entries total
            int m = idx >> 4, i2 = idx & 15;
            sAp[m][i2] = A2[(m0 + m) * 16 + i2];
        }
        __syncthreads();
        #pragma unroll 8
        for (int m = 0; m < 64; m++) {
            float x = X[(m0 + m) * NN + n];
            unsigned long long xx = dup2f(x);
            const ulonglong2* row = (const ulonglong2*)sAp[m];
            #pragma unroll
            for (int i4 = 0; i4 < 8; i4++) {
                ulonglong2 q = row[i4];
                acc[2 * i4]     = fma2(q.x, xx, acc[2 * i4]);
                acc[2 * i4 + 1] = fma2(q.y, xx, acc[2 * i4 + 1]);
            }
        }
    }
    #pragma unroll
    for (int i2 = 0; i2 < 16; i2++) g_AtX_p[i2][n] = acc[i2];
}

// ============================================================================
// Kernel 3: 200 FISTA iterations, one thread per column, all state in regs.
// Matvec uses packed f32x2 FMA over row-pairs; AtA broadcast from shared.
// ============================================================================
__global__ void __launch_bounds__(128) fista_kernel(float* __restrict__ out) {
    __shared__ __align__(16) unsigned long long sata[32][16];
    const int tid = threadIdx.x;
    const int n = blockIdx.x * 128 + tid;

    // cooperative copy of packed AtA (512 x 8B)
    #pragma unroll
    for (int k = 0; k < 4; k++)
        ((unsigned long long*)sata)[tid + k * 128] = ((const unsigned long long*)g_AtA_p)[tid + k * 128];

    const float step = g_step;
    const float nstep = -step;

    // natx[i2] = -(AtX[2i2][n], AtX[2i2+1][n])
    unsigned long long natx[16];
    #pragma unroll
    for (int i2 = 0; i2 < 16; i2++) {
        float lo, hi;
        unpack2f(g_AtX_p[i2][n], lo, hi);
        natx[i2] = pack2f(-lo, -hi);
    }
    __syncthreads();

    float s[32], y[32];
    #pragma unroll
    for (int i = 0; i < 32; i++) { s[i] = 0.0f; y[i] = 0.0f; }

    float t = 1.0f;
    #pragma unroll 1
    for (int it = 0; it < NITER; it++) {
        // z = AtA @ y - AtX   (packed over row pairs)
        unsigned long long z[16];
        #pragma unroll
        for (int i2 = 0; i2 < 16; i2++) z[i2] = natx[i2];

        #pragma unroll
        for (int j = 0; j < 32; j++) {
            unsigned long long yy = dup2f(y[j]);
            const ulonglong2* row = (const ulonglong2*)sata[j];
            #pragma unroll
            for (int i4 = 0; i4 < 8; i4++) {
                ulonglong2 q = row[i4];            // LDS.128, warp-broadcast
                z[2 * i4]     = fma2(q.x, yy, z[2 * i4]);
                z[2 * i4 + 1] = fma2(q.y, yy, z[2 * i4 + 1]);
            }
        }

        // momentum scalars (identical across threads)
        float tn = 0.5f * (1.0f + sqrtf(fmaf(4.0f * t, t, 1.0f)));
        float mu = (t - 1.0f) / tn;
        t = tn;

        // s_new = max(y - step*z, 0);  y = s_new + mu*(s_new - s);  s = s_new
        #pragma unroll
        for (int i2 = 0; i2 < 16; i2++) {
            float zlo, zhi;
            unpack2f(z[i2], zlo, zhi);
            int i0 = 2 * i2, i1 = 2 * i2 + 1;
            float s0 = fmaxf(fmaf(nstep, zlo, y[i0]), 0.0f);
            float s1 = fmaxf(fmaf(nstep, zhi, y[i1]), 0.0f);
            y[i0] = fmaf(mu, s0 - s[i0], s0);
            y[i1] = fmaf(mu, s1 - s[i1], s1);
            s[i0] = s0;
            s[i1] = s1;
        }
    }

    // S is [32, 32768] row-major
    #pragma unroll
    for (int i = 0; i < 32; i++)
        out[i * NN + n] = s[i];
}

// ============================================================================
extern "C" void kernel_launch(void* const* d_in, const int* in_sizes, int n_in,
                              void* d_out, int out_size) {
    const float* X = (const float*)d_in[0];
    const float* A = (const float*)d_in[1];
    // defensive: identify A by its element count (512*32 = 16384)
    if (n_in >= 2 && in_sizes[0] == MM * KK && in_sizes[1] != MM * KK) {
        A = (const float*)d_in[0];
        X = (const float*)d_in[1];
    }

    setup_kernel<<<1, 1024>>>(A);
    atx_kernel<<<NN / 256, 256>>>(X, A);
    fista_kernel<<<NN / 128, 128>>>((float*)d_out);
}